// round 14
// baseline (speedup 1.0000x reference)
#include <cuda_runtime.h>
#include <cuda_fp16.h>
#include <math.h>
#include <stdint.h>

// Problem constants
constexpr int Bc  = 4;
constexpr int Sq  = 2048;
constexpr int Dm  = 1024;
constexpr int Hh  = 16;
constexpr int HDd = 64;
constexpr int Mtot = Bc * Sq;           // 8192

// Scratch (device globals: allocation-free per harness rules)
__device__ __half g_xf[(size_t)Mtot * Dm];            // x fp16
__device__ __half g_wf[(size_t)4 * Dm * Dm];          // W fp16
__device__ __half g_cf[(size_t)Mtot * Dm];            // ctx fp16
__device__ __half g_qf[(size_t)Mtot * Dm];            // Q fp16 (scale*log2e folded)
__device__ __half g_kf[(size_t)Mtot * Dm];            // K fp16
__device__ __half g_vf[(size_t)Mtot * Dm];            // V fp16

// ---------------------------------------------------------------------------
// PTX helpers
// ---------------------------------------------------------------------------
__device__ __forceinline__ uint32_t smem_u32(const void* p) {
    uint32_t a;
    asm("{ .reg .u64 t; cvta.to.shared.u64 t, %1; cvt.u32.u64 %0, t; }" : "=r"(a) : "l"(p));
    return a;
}
__device__ __forceinline__ void ldm_x4(uint32_t (&r)[4], uint32_t saddr) {
    asm volatile("ldmatrix.sync.aligned.m8n8.x4.shared.b16 {%0,%1,%2,%3}, [%4];"
        : "=r"(r[0]), "=r"(r[1]), "=r"(r[2]), "=r"(r[3]) : "r"(saddr));
}
__device__ __forceinline__ void ldm_x4_t(uint32_t (&r)[4], uint32_t saddr) {
    asm volatile("ldmatrix.sync.aligned.m8n8.x4.trans.shared.b16 {%0,%1,%2,%3}, [%4];"
        : "=r"(r[0]), "=r"(r[1]), "=r"(r[2]), "=r"(r[3]) : "r"(saddr));
}
__device__ __forceinline__ void mma_fp16(float (&c)[4], const uint32_t (&a)[4],
                                         uint32_t b0, uint32_t b1) {
    asm volatile("mma.sync.aligned.m16n8k16.row.col.f32.f16.f16.f32 "
        "{%0,%1,%2,%3}, {%4,%5,%6,%7}, {%8,%9}, {%0,%1,%2,%3};"
        : "+f"(c[0]), "+f"(c[1]), "+f"(c[2]), "+f"(c[3])
        : "r"(a[0]), "r"(a[1]), "r"(a[2]), "r"(a[3]), "r"(b0), "r"(b1));
}
__device__ __forceinline__ void cp16(uint32_t dst, const void* src) {
    asm volatile("cp.async.cg.shared.global [%0], [%1], 16;" :: "r"(dst), "l"(src) : "memory");
}
#define CP_COMMIT() asm volatile("cp.async.commit_group;" ::: "memory")
#define CP_WAIT(n)  asm volatile("cp.async.wait_group %0;" :: "n"(n) : "memory")

__device__ __forceinline__ uint32_t hf2(float a, float b) {
    __half2 t = __floats2half2_rn(a, b);
    return *reinterpret_cast<uint32_t*>(&t);
}
__device__ __forceinline__ uint32_t swz(int row, int chunk) {
    return (uint32_t)(row * 128 + ((chunk ^ (row & 7)) * 16));
}

// ---------------------------------------------------------------------------
// Conversions: x -> fp16; weights -> fp16 (y-indexed over 4 weights)
// ---------------------------------------------------------------------------
__global__ __launch_bounds__(256) void cvt_x_kernel(const float* __restrict__ in,
                                                    __half* __restrict__ out, int n4)
{
    const int i = blockIdx.x * blockDim.x + threadIdx.x;
    if (i >= n4) return;
    const float4 v = ((const float4*)in)[i];
    uint2 u;
    u.x = hf2(v.x, v.y);
    u.y = hf2(v.z, v.w);
    ((uint2*)out)[i] = u;
}

__global__ __launch_bounds__(256) void cvt_w_kernel(
    const float* __restrict__ w0, const float* __restrict__ w1,
    const float* __restrict__ w2, const float* __restrict__ w3,
    __half* __restrict__ outw)
{
    const int n4 = Dm * Dm / 4;
    const int i = blockIdx.x * blockDim.x + threadIdx.x;
    if (i >= n4) return;
    const int wsel = blockIdx.y;
    const float* in = wsel == 0 ? w0 : wsel == 1 ? w1 : wsel == 2 ? w2 : w3;
    const size_t off = (size_t)wsel * n4 + i;
    const float4 v = ((const float4*)in)[i];
    uint2 u;
    u.x = hf2(v.x, v.y);
    u.y = hf2(v.z, v.w);
    ((uint2*)outw)[off] = u;
}

// ---------------------------------------------------------------------------
// HMMA fp16 GEMM (single-pass): out[M,N] = A_fp16[M,K] @ W[N,K]^T + bias
// 128x128 CTA tile, BK=64, 8 warps (2x4), cp.async 3-stage ring (96KB).
// ---------------------------------------------------------------------------
constexpr int BKg = 64;
constexpr int NKC = Dm / BKg;                  // 16
constexpr int ATILE = 128 * 128;               // 16 KB
constexpr int STAGE_BYTES = 2 * ATILE;         // 32 KB (A + B)
constexpr int GEMM_SMEM = 3 * STAGE_BYTES;     // 96 KB

template <bool SPLIT>
__global__ __launch_bounds__(256, 2) void hmma_gemm_kernel(
    const __half* __restrict__ Af,
    const __half* __restrict__ B0, const __half* __restrict__ B1,
    const __half* __restrict__ B2,
    const float* __restrict__ bias0, const float* __restrict__ bias1,
    const float* __restrict__ bias2,
    float* __restrict__ outF,
    __half* __restrict__ oh0, __half* __restrict__ oh1,
    __half* __restrict__ oh2,
    float scale0)
{
    extern __shared__ char sm[];
    const uint32_t smb = smem_u32(sm);
    const int z    = blockIdx.z;
    const __half* Bw  = z == 0 ? B0 : z == 1 ? B1 : B2;
    const float* bias = z == 0 ? bias0 : z == 1 ? bias1 : bias2;
    __half* outH      = z == 0 ? oh0 : z == 1 ? oh1 : oh2;
    const float scale = (SPLIT && z == 0) ? scale0 : 1.0f;

    const int t    = threadIdx.x;
    const int wid  = t >> 5;
    const int lane = t & 31;
    const int m0   = blockIdx.y * 128;
    const int n0   = blockIdx.x * 128;
    const int wm   = (wid & 1) * 64;
    const int wn   = (wid >> 1) * 32;

    auto load_stage = [&](int s, int kc) {
        const uint32_t ab = smb + s * STAGE_BYTES;
        const uint32_t bb = ab + ATILE;
#pragma unroll
        for (int i = 0; i < 4; i++) {
            const int idx = t + i * 256;
            const int row = idx >> 3;
            const int c   = idx & 7;
            const int kofs = kc * BKg + c * 8;
            cp16(ab + swz(row, c), Af + (size_t)(m0 + row) * Dm + kofs);
            cp16(bb + swz(row, c), Bw + (size_t)(n0 + row) * Dm + kofs);
        }
        CP_COMMIT();
    };

    float acc[4][4][4];
#pragma unroll
    for (int i = 0; i < 4; i++)
#pragma unroll
        for (int j = 0; j < 4; j++)
#pragma unroll
            for (int r = 0; r < 4; r++) acc[i][j][r] = 0.0f;

    load_stage(0, 0);
    load_stage(1, 1);

    const int lrow = lane & 15;
    const int lsel = lane >> 4;

    int s = 0;
    for (int kc = 0; kc < NKC; kc++) {
        if (kc + 1 < NKC) { CP_WAIT(1); } else { CP_WAIT(0); }
        __syncthreads();
        if (kc + 2 < NKC) {
            int s2 = s + 2; if (s2 >= 3) s2 -= 3;
            load_stage(s2, kc + 2);
        }

        const uint32_t ab = smb + s * STAGE_BYTES;
        const uint32_t bb = ab + ATILE;

#pragma unroll
        for (int k16 = 0; k16 < 4; k16++) {
            const int ch = k16 * 2 + lsel;
            uint32_t a_f[4][4];
#pragma unroll
            for (int mt = 0; mt < 4; mt++)
                ldm_x4(a_f[mt], ab + swz(wm + mt * 16 + lrow, ch));
            uint32_t b_f[2][4];
#pragma unroll
            for (int nt = 0; nt < 2; nt++)
                ldm_x4(b_f[nt], bb + swz(wn + nt * 16 + lrow, ch));
#pragma unroll
            for (int mt = 0; mt < 4; mt++) {
#pragma unroll
                for (int n8 = 0; n8 < 4; n8++) {
                    const int nt = n8 >> 1, sl = n8 & 1;
                    mma_fp16(acc[mt][n8], a_f[mt], b_f[nt][sl], b_f[nt][sl + 2]);
                }
            }
        }
        if (++s == 3) s = 0;
    }

#pragma unroll
    for (int mt = 0; mt < 4; mt++) {
#pragma unroll
        for (int n8 = 0; n8 < 4; n8++) {
            const int r0 = m0 + wm + mt * 16 + (lane >> 2);
            const int c0 = n0 + wn + n8 * 8 + (lane & 3) * 2;
#pragma unroll
            for (int half = 0; half < 2; half++) {
                const int m = r0 + half * 8;
                const int b_ = m / Sq;
                const int s_ = m % Sq;
                const float v0 = (acc[mt][n8][half * 2 + 0] + bias[c0]) * scale;
                const float v1 = (acc[mt][n8][half * 2 + 1] + bias[c0 + 1]) * scale;
                if (SPLIT) {
                    const int h_ = c0 >> 6;
                    const int d_ = c0 & 63;
                    const size_t off =
                        ((((size_t)(b_ * Hh + h_)) * Sq + s_) * HDd + d_) >> 1;
                    ((uint32_t*)outH)[off] = hf2(v0, v1);
                } else {
                    float* dst = outF + (size_t)m * Dm + c0;
                    dst[0] = v0; dst[1] = v1;
                }
            }
        }
    }
}

// ---------------------------------------------------------------------------
// HMMA fp16 flash attention: CTA = (64 queries, head, batch), 4 warps.
// Q fp16 (8KB), K+V fp16 double-buffered (2x16KB), mask 2x256B -> 41KB/CTA.
// Register-dieted (short-lived K/V/P fragments) for 5 CTAs/SM.
// Base-2 softmax; pad mask via ballot; alpha==1 rescale skip.
// Longest-first: qt = gridDim.x - 1 - blockIdx.x.
// ---------------------------------------------------------------------------
constexpr int FA_Q    = 8192;
constexpr int FA_KVST = 16384;                 // K 8KB + V 8KB
constexpr int FA_MOFF = FA_Q + 2 * FA_KVST;    // 40960
constexpr int FA_SMEM = FA_MOFF + 512;         // 41472

__global__ __launch_bounds__(128, 5) void fa_hmma_kernel(
    const __half* __restrict__ Qf,
    const __half* __restrict__ Kf,
    const __half* __restrict__ Vf,
    const int* __restrict__ maskg,
    __half* __restrict__ Cf)
{
    extern __shared__ char sm[];
    const uint32_t smb = smem_u32(sm);
    const int t    = threadIdx.x;
    const int w    = t >> 5;
    const int lane = t & 31;
    const int qt   = gridDim.x - 1 - blockIdx.x;   // longest-first
    const int h    = blockIdx.y;
    const int b    = blockIdx.z;
    const size_t hb = ((size_t)(b * Hh + h)) * Sq * HDd;

    const uint32_t qfb = smb;

    auto load_kv = [&](int s, int kt2) {
        const uint32_t kb = smb + FA_Q + s * FA_KVST;
        const char* sK = (const char*)(Kf + hb + (size_t)kt2 * 64 * HDd);
        const char* sV = (const char*)(Vf + hb + (size_t)kt2 * 64 * HDd);
#pragma unroll
        for (int i = 0; i < 4; i++) {
            const int idx = t + i * 128;
            const int row = idx >> 3, c = idx & 7;
            cp16(kb + swz(row, c), sK + idx * 16);
            cp16(kb + 8192 + swz(row, c), sV + idx * 16);
        }
        if (t < 16) cp16(smb + FA_MOFF + s * 256 + t * 16,
                         maskg + b * Sq + kt2 * 64 + t * 4);
        CP_COMMIT();
    };

    // Prologue: Q tile + K/V(0) + mask(0) in one group.
    {
        const char* srcQ = (const char*)(Qf + hb + (size_t)qt * 64 * HDd);
#pragma unroll
        for (int i = 0; i < 4; i++) {
            const int idx = t + i * 128;
            const int row = idx >> 3, c = idx & 7;
            cp16(qfb + swz(row, c), srcQ + idx * 16);
        }
    }
    load_kv(0, 0);

    const int lrow  = lane & 15;
    const int lsel  = lane >> 4;
    const int rl    = lane >> 2;
    const int cbase = (lane & 3) * 2;
    const int wr0   = w * 16;

    float m_i[2] = {-INFINITY, -INFINITY};
    float l_i[2] = {0.0f, 0.0f};
    float o[8][4];
#pragma unroll
    for (int n8 = 0; n8 < 8; n8++)
#pragma unroll
        for (int c = 0; c < 4; c++) o[n8][c] = 0.0f;

    for (int kt2 = 0; kt2 <= qt; kt2++) {
        const int s = kt2 & 1;

        __syncthreads();                 // stage s free
        if (kt2 < qt) { load_kv(s ^ 1, kt2 + 1); CP_WAIT(1); }
        else          { CP_WAIT(0); }
        __syncthreads();                 // stage s visible

        const uint32_t kfb = smb + FA_Q + s * FA_KVST;
        const uint32_t vfb = kfb + 8192;
        const int* msk = (const int*)(sm + FA_MOFF + s * 256);

        // ---- S = Q @ K^T (K frags short-lived: 4 regs) ----
        float sc[8][4];
#pragma unroll
        for (int n8 = 0; n8 < 8; n8++)
#pragma unroll
            for (int c = 0; c < 4; c++) sc[n8][c] = 0.0f;

#pragma unroll
        for (int k16 = 0; k16 < 4; k16++) {
            const int ch = k16 * 2 + lsel;
            uint32_t qf[4];
            ldm_x4(qf, qfb + swz(wr0 + lrow, ch));
#pragma unroll
            for (int nt = 0; nt < 4; nt++) {
                uint32_t kf4[4];
                ldm_x4(kf4, kfb + swz(nt * 16 + lrow, ch));
                mma_fp16(sc[2 * nt + 0], qf, kf4[0], kf4[2]);
                mma_fp16(sc[2 * nt + 1], qf, kf4[1], kf4[3]);
            }
        }

        // ---- masking: causal on diagonal; pad via ballot bitmask ----
        if (kt2 == qt) {
            const int qi0 = qt * 64 + wr0 + rl;
#pragma unroll
            for (int n8 = 0; n8 < 8; n8++) {
#pragma unroll
                for (int c = 0; c < 4; c++) {
                    const int kj = kt2 * 64 + n8 * 8 + cbase + (c & 1);
                    const int qi = qi0 + (c >> 1) * 8;
                    if (kj > qi) sc[n8][c] = -INFINITY;
                }
            }
        }
        const uint32_t bm0 = __ballot_sync(0xffffffffu, msk[lane] != 0);
        const uint32_t bm1 = __ballot_sync(0xffffffffu, msk[lane + 32] != 0);
        if ((bm0 & bm1) != 0xffffffffu) {
#pragma unroll
            for (int n8 = 0; n8 < 8; n8++) {
#pragma unroll
                for (int c = 0; c < 4; c++) {
                    const int colL = n8 * 8 + cbase + (c & 1);
                    const uint32_t bit =
                        (colL < 32 ? bm0 >> colL : bm1 >> (colL - 32)) & 1u;
                    if (!bit) sc[n8][c] = -1e9f;
                }
            }
        }

        // ---- online softmax in base-2 (rows rl, rl+8) ----
#pragma unroll
        for (int r = 0; r < 2; r++) {
            float mx = -INFINITY;
#pragma unroll
            for (int n8 = 0; n8 < 8; n8++)
                mx = fmaxf(mx, fmaxf(sc[n8][2 * r], sc[n8][2 * r + 1]));
            mx = fmaxf(mx, __shfl_xor_sync(0xffffffffu, mx, 1));
            mx = fmaxf(mx, __shfl_xor_sync(0xffffffffu, mx, 2));
            const float mnew = fmaxf(m_i[r], mx);
            float sum = 0.0f;
#pragma unroll
            for (int n8 = 0; n8 < 8; n8++) {
                const float p0 = exp2f(sc[n8][2 * r]     - mnew);
                const float p1 = exp2f(sc[n8][2 * r + 1] - mnew);
                sc[n8][2 * r] = p0; sc[n8][2 * r + 1] = p1;
                sum += p0 + p1;
            }
            sum += __shfl_xor_sync(0xffffffffu, sum, 1);
            sum += __shfl_xor_sync(0xffffffffu, sum, 2);
            if (mnew == m_i[r]) {            // common case: max unchanged
                l_i[r] += sum;
            } else {
                const float alpha = exp2f(m_i[r] - mnew);
                l_i[r] = l_i[r] * alpha + sum;
                m_i[r] = mnew;
#pragma unroll
                for (int n8 = 0; n8 < 8; n8++) {
                    o[n8][2 * r] *= alpha; o[n8][2 * r + 1] *= alpha;
                }
            }
        }

        // ---- O += P @ V (V frags short-lived: 4 regs; P converted per j) ----
#pragma unroll
        for (int j = 0; j < 4; j++) {
            uint32_t pa4[4];
#pragma unroll
            for (int u = 0; u < 4; u++) {
                const int tile = 2 * j + (u >> 1);
                const int ci   = (u & 1) * 2;
                pa4[u] = hf2(sc[tile][ci], sc[tile][ci + 1]);
            }
            const int mrow = 16 * j + ((lane >> 3) & 1) * 8 + (lane & 7);
#pragma unroll
            for (int hp = 0; hp < 4; hp++) {
                const int chv = hp * 2 + (lane >> 4);
                uint32_t vf4[4];
                ldm_x4_t(vf4, vfb + swz(mrow, chv));
                mma_fp16(o[2 * hp + 0], pa4, vf4[0], vf4[1]);
                mma_fp16(o[2 * hp + 1], pa4, vf4[2], vf4[3]);
            }
        }
    }

    // ---- normalize + write ctx fp16 [B,S,D] ----
#pragma unroll
    for (int r = 0; r < 2; r++) {
        const float inv = 1.0f / l_i[r];
        const int m = qt * 64 + wr0 + rl + r * 8;
        const size_t rowoff = ((size_t)b * Sq + m) * Dm + h * HDd;
#pragma unroll
        for (int n8 = 0; n8 < 8; n8++) {
            const int col = n8 * 8 + cbase;
            *((uint32_t*)(Cf + rowoff + col)) =
                hf2(o[n8][2 * r] * inv, o[n8][2 * r + 1] * inv);
        }
    }
}

// ---------------------------------------------------------------------------
// Launch
// ---------------------------------------------------------------------------
extern "C" void kernel_launch(void* const* d_in, const int* in_sizes, int n_in,
                              void* d_out, int out_size)
{
    const float* x  = nullptr;
    const int*   am = nullptr;
    const float* Ws[4] = {nullptr, nullptr, nullptr, nullptr};
    const float* bs[4] = {nullptr, nullptr, nullptr, nullptr};
    int wi = 0, bi = 0;
    for (int i = 0; i < n_in; i++) {
        const long sz = in_sizes[i];
        if (sz == (long)Mtot * Dm)      x = (const float*)d_in[i];
        else if (sz == (long)Mtot)      am = (const int*)d_in[i];
        else if (sz == (long)Dm * Dm) { if (wi < 4) Ws[wi++] = (const float*)d_in[i]; }
        else if (sz == (long)Dm)      { if (bi < 4) bs[bi++] = (const float*)d_in[i]; }
    }

    __half *xf, *wf, *cf, *qf, *kf, *vf;
    cudaGetSymbolAddress((void**)&xf, g_xf);
    cudaGetSymbolAddress((void**)&wf, g_wf);
    cudaGetSymbolAddress((void**)&cf, g_cf);
    cudaGetSymbolAddress((void**)&qf, g_qf);
    cudaGetSymbolAddress((void**)&kf, g_kf);
    cudaGetSymbolAddress((void**)&vf, g_vf);

    cudaFuncSetAttribute(hmma_gemm_kernel<true>,
                         cudaFuncAttributeMaxDynamicSharedMemorySize, GEMM_SMEM);
    cudaFuncSetAttribute(hmma_gemm_kernel<false>,
                         cudaFuncAttributeMaxDynamicSharedMemorySize, GEMM_SMEM);
    cudaFuncSetAttribute(fa_hmma_kernel,
                         cudaFuncAttributeMaxDynamicSharedMemorySize, FA_SMEM);

    // Conversions
    const int n4x = Mtot * Dm / 4;
    const int n4w = Dm * Dm / 4;
    cvt_x_kernel<<<(n4x + 255) / 256, 256>>>(x, xf, n4x);
    cvt_w_kernel<<<dim3((n4w + 255) / 256, 4), 256>>>(
        Ws[0], Ws[1], Ws[2], Ws[3], wf);

    const size_t WSZ = (size_t)Dm * Dm;

    // Fused Q/K/V projections (single-pass fp16); Q carries 0.125*log2e.
    const float QSCALE = 0.125f * 1.4426950408889634f;
    const dim3 gqkv(Dm / 128, Mtot / 128, 3);
    hmma_gemm_kernel<true><<<gqkv, 256, GEMM_SMEM>>>(
        xf,
        wf + 0 * WSZ, wf + 1 * WSZ, wf + 2 * WSZ,
        bs[0], bs[1], bs[2],
        nullptr,
        qf, kf, vf,
        QSCALE);

    // Attention (single-pass QK^T and PV, base-2 softmax, 5 CTAs/SM)
    const dim3 ga(Sq / 64, Hh, Bc);
    fa_hmma_kernel<<<ga, 128, FA_SMEM>>>(qf, kf, vf, am, cf);

    // Output projection (single-pass fp16)
    const dim3 gg(Dm / 128, Mtot / 128, 1);
    hmma_gemm_kernel<false><<<gg, 256, GEMM_SMEM>>>(
        cf,
        wf + 3 * WSZ, wf + 3 * WSZ, wf + 3 * WSZ,
        bs[3], bs[3], bs[3],
        (float*)d_out,
        nullptr, nullptr, nullptr,
        1.0f);
}

// round 15
// speedup vs baseline: 1.0402x; 1.0402x over previous
#include <cuda_runtime.h>
#include <cuda_fp16.h>
#include <math.h>
#include <stdint.h>

// Problem constants
constexpr int Bc  = 4;
constexpr int Sq  = 2048;
constexpr int Dm  = 1024;
constexpr int Hh  = 16;
constexpr int HDd = 64;
constexpr int Mtot = Bc * Sq;           // 8192

// Scratch (device globals: allocation-free per harness rules)
__device__ __half g_xf[(size_t)Mtot * Dm];            // x fp16
__device__ __half g_wf[(size_t)4 * Dm * Dm];          // W fp16
__device__ __half g_cf[(size_t)Mtot * Dm];            // ctx fp16
__device__ __half g_qf[(size_t)Mtot * Dm];            // Q fp16 (scale*log2e folded)
__device__ __half g_kf[(size_t)Mtot * Dm];            // K fp16
__device__ __half g_vf[(size_t)Mtot * Dm];            // V fp16

// ---------------------------------------------------------------------------
// PTX helpers
// ---------------------------------------------------------------------------
__device__ __forceinline__ uint32_t smem_u32(const void* p) {
    uint32_t a;
    asm("{ .reg .u64 t; cvta.to.shared.u64 t, %1; cvt.u32.u64 %0, t; }" : "=r"(a) : "l"(p));
    return a;
}
__device__ __forceinline__ void ldm_x4(uint32_t (&r)[4], uint32_t saddr) {
    asm volatile("ldmatrix.sync.aligned.m8n8.x4.shared.b16 {%0,%1,%2,%3}, [%4];"
        : "=r"(r[0]), "=r"(r[1]), "=r"(r[2]), "=r"(r[3]) : "r"(saddr));
}
__device__ __forceinline__ void ldm_x4_t(uint32_t (&r)[4], uint32_t saddr) {
    asm volatile("ldmatrix.sync.aligned.m8n8.x4.trans.shared.b16 {%0,%1,%2,%3}, [%4];"
        : "=r"(r[0]), "=r"(r[1]), "=r"(r[2]), "=r"(r[3]) : "r"(saddr));
}
__device__ __forceinline__ void mma_fp16(float (&c)[4], const uint32_t (&a)[4],
                                         uint32_t b0, uint32_t b1) {
    asm volatile("mma.sync.aligned.m16n8k16.row.col.f32.f16.f16.f32 "
        "{%0,%1,%2,%3}, {%4,%5,%6,%7}, {%8,%9}, {%0,%1,%2,%3};"
        : "+f"(c[0]), "+f"(c[1]), "+f"(c[2]), "+f"(c[3])
        : "r"(a[0]), "r"(a[1]), "r"(a[2]), "r"(a[3]), "r"(b0), "r"(b1));
}
__device__ __forceinline__ void cp16(uint32_t dst, const void* src) {
    asm volatile("cp.async.cg.shared.global [%0], [%1], 16;" :: "r"(dst), "l"(src) : "memory");
}
#define CP_COMMIT() asm volatile("cp.async.commit_group;" ::: "memory")
#define CP_WAIT(n)  asm volatile("cp.async.wait_group %0;" :: "n"(n) : "memory")

__device__ __forceinline__ uint32_t hf2(float a, float b) {
    __half2 t = __floats2half2_rn(a, b);
    return *reinterpret_cast<uint32_t*>(&t);
}
__device__ __forceinline__ uint32_t swz(int row, int chunk) {
    return (uint32_t)(row * 128 + ((chunk ^ (row & 7)) * 16));
}

// ---------------------------------------------------------------------------
// Conversions: x -> fp16; weights -> fp16 (y-indexed over 4 weights)
// ---------------------------------------------------------------------------
__global__ __launch_bounds__(256) void cvt_x_kernel(const float* __restrict__ in,
                                                    __half* __restrict__ out, int n4)
{
    const int i = blockIdx.x * blockDim.x + threadIdx.x;
    if (i >= n4) return;
    const float4 v = ((const float4*)in)[i];
    uint2 u;
    u.x = hf2(v.x, v.y);
    u.y = hf2(v.z, v.w);
    ((uint2*)out)[i] = u;
}

__global__ __launch_bounds__(256) void cvt_w_kernel(
    const float* __restrict__ w0, const float* __restrict__ w1,
    const float* __restrict__ w2, const float* __restrict__ w3,
    __half* __restrict__ outw)
{
    const int n4 = Dm * Dm / 4;
    const int i = blockIdx.x * blockDim.x + threadIdx.x;
    if (i >= n4) return;
    const int wsel = blockIdx.y;
    const float* in = wsel == 0 ? w0 : wsel == 1 ? w1 : wsel == 2 ? w2 : w3;
    const size_t off = (size_t)wsel * n4 + i;
    const float4 v = ((const float4*)in)[i];
    uint2 u;
    u.x = hf2(v.x, v.y);
    u.y = hf2(v.z, v.w);
    ((uint2*)outw)[off] = u;
}

// ---------------------------------------------------------------------------
// HMMA fp16 GEMM (single-pass): out[M,N] = A_fp16[M,K] @ W[N,K]^T + bias
// 128x128 CTA tile, BK=64, 8 warps (2x4), cp.async 3-stage ring (96KB).
// ---------------------------------------------------------------------------
constexpr int BKg = 64;
constexpr int NKC = Dm / BKg;                  // 16
constexpr int ATILE = 128 * 128;               // 16 KB
constexpr int STAGE_BYTES = 2 * ATILE;         // 32 KB (A + B)
constexpr int GEMM_SMEM = 3 * STAGE_BYTES;     // 96 KB

template <bool SPLIT>
__global__ __launch_bounds__(256, 2) void hmma_gemm_kernel(
    const __half* __restrict__ Af,
    const __half* __restrict__ B0, const __half* __restrict__ B1,
    const __half* __restrict__ B2,
    const float* __restrict__ bias0, const float* __restrict__ bias1,
    const float* __restrict__ bias2,
    float* __restrict__ outF,
    __half* __restrict__ oh0, __half* __restrict__ oh1,
    __half* __restrict__ oh2,
    float scale0)
{
    extern __shared__ char sm[];
    const uint32_t smb = smem_u32(sm);
    const int z    = blockIdx.z;
    const __half* Bw  = z == 0 ? B0 : z == 1 ? B1 : B2;
    const float* bias = z == 0 ? bias0 : z == 1 ? bias1 : bias2;
    __half* outH      = z == 0 ? oh0 : z == 1 ? oh1 : oh2;
    const float scale = (SPLIT && z == 0) ? scale0 : 1.0f;

    const int t    = threadIdx.x;
    const int wid  = t >> 5;
    const int lane = t & 31;
    const int m0   = blockIdx.y * 128;
    const int n0   = blockIdx.x * 128;
    const int wm   = (wid & 1) * 64;
    const int wn   = (wid >> 1) * 32;

    auto load_stage = [&](int s, int kc) {
        const uint32_t ab = smb + s * STAGE_BYTES;
        const uint32_t bb = ab + ATILE;
#pragma unroll
        for (int i = 0; i < 4; i++) {
            const int idx = t + i * 256;
            const int row = idx >> 3;
            const int c   = idx & 7;
            const int kofs = kc * BKg + c * 8;
            cp16(ab + swz(row, c), Af + (size_t)(m0 + row) * Dm + kofs);
            cp16(bb + swz(row, c), Bw + (size_t)(n0 + row) * Dm + kofs);
        }
        CP_COMMIT();
    };

    float acc[4][4][4];
#pragma unroll
    for (int i = 0; i < 4; i++)
#pragma unroll
        for (int j = 0; j < 4; j++)
#pragma unroll
            for (int r = 0; r < 4; r++) acc[i][j][r] = 0.0f;

    load_stage(0, 0);
    load_stage(1, 1);

    const int lrow = lane & 15;
    const int lsel = lane >> 4;

    int s = 0;
    for (int kc = 0; kc < NKC; kc++) {
        if (kc + 1 < NKC) { CP_WAIT(1); } else { CP_WAIT(0); }
        __syncthreads();
        if (kc + 2 < NKC) {
            int s2 = s + 2; if (s2 >= 3) s2 -= 3;
            load_stage(s2, kc + 2);
        }

        const uint32_t ab = smb + s * STAGE_BYTES;
        const uint32_t bb = ab + ATILE;

#pragma unroll
        for (int k16 = 0; k16 < 4; k16++) {
            const int ch = k16 * 2 + lsel;
            uint32_t a_f[4][4];
#pragma unroll
            for (int mt = 0; mt < 4; mt++)
                ldm_x4(a_f[mt], ab + swz(wm + mt * 16 + lrow, ch));
            uint32_t b_f[2][4];
#pragma unroll
            for (int nt = 0; nt < 2; nt++)
                ldm_x4(b_f[nt], bb + swz(wn + nt * 16 + lrow, ch));
#pragma unroll
            for (int mt = 0; mt < 4; mt++) {
#pragma unroll
                for (int n8 = 0; n8 < 4; n8++) {
                    const int nt = n8 >> 1, sl = n8 & 1;
                    mma_fp16(acc[mt][n8], a_f[mt], b_f[nt][sl], b_f[nt][sl + 2]);
                }
            }
        }
        if (++s == 3) s = 0;
    }

#pragma unroll
    for (int mt = 0; mt < 4; mt++) {
#pragma unroll
        for (int n8 = 0; n8 < 4; n8++) {
            const int r0 = m0 + wm + mt * 16 + (lane >> 2);
            const int c0 = n0 + wn + n8 * 8 + (lane & 3) * 2;
#pragma unroll
            for (int half = 0; half < 2; half++) {
                const int m = r0 + half * 8;
                const int b_ = m / Sq;
                const int s_ = m % Sq;
                const float v0 = (acc[mt][n8][half * 2 + 0] + bias[c0]) * scale;
                const float v1 = (acc[mt][n8][half * 2 + 1] + bias[c0 + 1]) * scale;
                if (SPLIT) {
                    const int h_ = c0 >> 6;
                    const int d_ = c0 & 63;
                    const size_t off =
                        ((((size_t)(b_ * Hh + h_)) * Sq + s_) * HDd + d_) >> 1;
                    ((uint32_t*)outH)[off] = hf2(v0, v1);
                } else {
                    float* dst = outF + (size_t)m * Dm + c0;
                    dst[0] = v0; dst[1] = v1;
                }
            }
        }
    }
}

// ---------------------------------------------------------------------------
// HMMA fp16 flash attention (round-13 structure): CTA = (64 queries, head,
// batch), 4 warps. Q fp16 (8KB), K+V fp16 double-buffered (2x16KB),
// mask 2x256B -> 41KB/CTA, 4 CTAs/SM. Full fragment buffers for ILP.
// Base-2 softmax; pad mask via ballot; alpha==1 rescale skip.
// Longest-first: qt = gridDim.x - 1 - blockIdx.x.
// ---------------------------------------------------------------------------
constexpr int FA_Q    = 8192;
constexpr int FA_KVST = 16384;                 // K 8KB + V 8KB
constexpr int FA_MOFF = FA_Q + 2 * FA_KVST;    // 40960
constexpr int FA_SMEM = FA_MOFF + 512;         // 41472

__global__ __launch_bounds__(128, 4) void fa_hmma_kernel(
    const __half* __restrict__ Qf,
    const __half* __restrict__ Kf,
    const __half* __restrict__ Vf,
    const int* __restrict__ maskg,
    __half* __restrict__ Cf)
{
    extern __shared__ char sm[];
    const uint32_t smb = smem_u32(sm);
    const int t    = threadIdx.x;
    const int w    = t >> 5;
    const int lane = t & 31;
    const int qt   = gridDim.x - 1 - blockIdx.x;   // longest-first
    const int h    = blockIdx.y;
    const int b    = blockIdx.z;
    const size_t hb = ((size_t)(b * Hh + h)) * Sq * HDd;

    const uint32_t qfb = smb;

    auto load_kv = [&](int s, int kt2) {
        const uint32_t kb = smb + FA_Q + s * FA_KVST;
        const char* sK = (const char*)(Kf + hb + (size_t)kt2 * 64 * HDd);
        const char* sV = (const char*)(Vf + hb + (size_t)kt2 * 64 * HDd);
#pragma unroll
        for (int i = 0; i < 4; i++) {
            const int idx = t + i * 128;
            const int row = idx >> 3, c = idx & 7;
            cp16(kb + swz(row, c), sK + idx * 16);
            cp16(kb + 8192 + swz(row, c), sV + idx * 16);
        }
        if (t < 16) cp16(smb + FA_MOFF + s * 256 + t * 16,
                         maskg + b * Sq + kt2 * 64 + t * 4);
        CP_COMMIT();
    };

    // Prologue: Q tile + K/V(0) + mask(0) in one group.
    {
        const char* srcQ = (const char*)(Qf + hb + (size_t)qt * 64 * HDd);
#pragma unroll
        for (int i = 0; i < 4; i++) {
            const int idx = t + i * 128;
            const int row = idx >> 3, c = idx & 7;
            cp16(qfb + swz(row, c), srcQ + idx * 16);
        }
    }
    load_kv(0, 0);

    const int lrow  = lane & 15;
    const int lsel  = lane >> 4;
    const int rl    = lane >> 2;
    const int cbase = (lane & 3) * 2;
    const int wr0   = w * 16;

    float m_i[2] = {-INFINITY, -INFINITY};
    float l_i[2] = {0.0f, 0.0f};
    float o[8][4];
#pragma unroll
    for (int n8 = 0; n8 < 8; n8++)
#pragma unroll
        for (int c = 0; c < 4; c++) o[n8][c] = 0.0f;

    for (int kt2 = 0; kt2 <= qt; kt2++) {
        const int s = kt2 & 1;

        __syncthreads();                 // stage s free (reads of prev use done)
        if (kt2 < qt) { load_kv(s ^ 1, kt2 + 1); CP_WAIT(1); }
        else          { CP_WAIT(0); }
        __syncthreads();                 // stage s visible

        const uint32_t kfb = smb + FA_Q + s * FA_KVST;
        const uint32_t vfb = kfb + 8192;
        const int* msk = (const int*)(sm + FA_MOFF + s * 256);

        // ---- S = Q @ K^T (single pass; scores pre-scaled by 0.125*log2e) ----
        float sc[8][4];
#pragma unroll
        for (int n8 = 0; n8 < 8; n8++)
#pragma unroll
            for (int c = 0; c < 4; c++) sc[n8][c] = 0.0f;

#pragma unroll
        for (int k16 = 0; k16 < 4; k16++) {
            const int ch = k16 * 2 + lsel;
            uint32_t qf[4];
            ldm_x4(qf, qfb + swz(wr0 + lrow, ch));
            uint32_t kf[4][4];
#pragma unroll
            for (int nt = 0; nt < 4; nt++)
                ldm_x4(kf[nt], kfb + swz(nt * 16 + lrow, ch));
#pragma unroll
            for (int n8 = 0; n8 < 8; n8++) {
                const int nt = n8 >> 1, sl = n8 & 1;
                mma_fp16(sc[n8], qf, kf[nt][sl], kf[nt][sl + 2]);
            }
        }

        // ---- masking: causal on diagonal; pad via ballot bitmask ----
        if (kt2 == qt) {
            const int qi0 = qt * 64 + wr0 + rl;
#pragma unroll
            for (int n8 = 0; n8 < 8; n8++) {
#pragma unroll
                for (int c = 0; c < 4; c++) {
                    const int kj = kt2 * 64 + n8 * 8 + cbase + (c & 1);
                    const int qi = qi0 + (c >> 1) * 8;
                    if (kj > qi) sc[n8][c] = -INFINITY;
                }
            }
        }
        const uint32_t bm0 = __ballot_sync(0xffffffffu, msk[lane] != 0);
        const uint32_t bm1 = __ballot_sync(0xffffffffu, msk[lane + 32] != 0);
        if ((bm0 & bm1) != 0xffffffffu) {
#pragma unroll
            for (int n8 = 0; n8 < 8; n8++) {
#pragma unroll
                for (int c = 0; c < 4; c++) {
                    const int colL = n8 * 8 + cbase + (c & 1);
                    const uint32_t bit =
                        (colL < 32 ? bm0 >> colL : bm1 >> (colL - 32)) & 1u;
                    if (!bit) sc[n8][c] = -1e9f;
                }
            }
        }

        // ---- online softmax in base-2 (rows rl, rl+8) ----
#pragma unroll
        for (int r = 0; r < 2; r++) {
            float mx = -INFINITY;
#pragma unroll
            for (int n8 = 0; n8 < 8; n8++)
                mx = fmaxf(mx, fmaxf(sc[n8][2 * r], sc[n8][2 * r + 1]));
            mx = fmaxf(mx, __shfl_xor_sync(0xffffffffu, mx, 1));
            mx = fmaxf(mx, __shfl_xor_sync(0xffffffffu, mx, 2));
            const float mnew = fmaxf(m_i[r], mx);
            float sum = 0.0f;
#pragma unroll
            for (int n8 = 0; n8 < 8; n8++) {
                const float p0 = exp2f(sc[n8][2 * r]     - mnew);
                const float p1 = exp2f(sc[n8][2 * r + 1] - mnew);
                sc[n8][2 * r] = p0; sc[n8][2 * r + 1] = p1;
                sum += p0 + p1;
            }
            sum += __shfl_xor_sync(0xffffffffu, sum, 1);
            sum += __shfl_xor_sync(0xffffffffu, sum, 2);
            if (mnew == m_i[r]) {            // common case: max unchanged
                l_i[r] += sum;
            } else {
                const float alpha = exp2f(m_i[r] - mnew);
                l_i[r] = l_i[r] * alpha + sum;
                m_i[r] = mnew;
#pragma unroll
                for (int n8 = 0; n8 < 8; n8++) {
                    o[n8][2 * r] *= alpha; o[n8][2 * r + 1] *= alpha;
                }
            }
        }

        // ---- P -> single fp16 A-fragments ----
        uint32_t pa[4][4];
#pragma unroll
        for (int j = 0; j < 4; j++) {
#pragma unroll
            for (int u = 0; u < 4; u++) {
                const int tile = 2 * j + (u >> 1);
                const int ci   = (u & 1) * 2;
                pa[j][u] = hf2(sc[tile][ci], sc[tile][ci + 1]);
            }
        }

        // ---- O += P @ V (single pass) ----
#pragma unroll
        for (int j = 0; j < 4; j++) {
            const int mrow = 16 * j + ((lane >> 3) & 1) * 8 + (lane & 7);
            uint32_t vf[4][4];
#pragma unroll
            for (int hp = 0; hp < 4; hp++) {
                const int chv = hp * 2 + (lane >> 4);
                ldm_x4_t(vf[hp], vfb + swz(mrow, chv));
            }
#pragma unroll
            for (int n8 = 0; n8 < 8; n8++) {
                const int hp = n8 >> 1, q_ = n8 & 1;
                mma_fp16(o[n8], pa[j], vf[hp][2 * q_], vf[hp][2 * q_ + 1]);
            }
        }
    }

    // ---- normalize + write ctx fp16 [B,S,D] ----
#pragma unroll
    for (int r = 0; r < 2; r++) {
        const float inv = 1.0f / l_i[r];
        const int m = qt * 64 + wr0 + rl + r * 8;
        const size_t rowoff = ((size_t)b * Sq + m) * Dm + h * HDd;
#pragma unroll
        for (int n8 = 0; n8 < 8; n8++) {
            const int col = n8 * 8 + cbase;
            *((uint32_t*)(Cf + rowoff + col)) =
                hf2(o[n8][2 * r] * inv, o[n8][2 * r + 1] * inv);
        }
    }
}

// ---------------------------------------------------------------------------
// Launch
// ---------------------------------------------------------------------------
extern "C" void kernel_launch(void* const* d_in, const int* in_sizes, int n_in,
                              void* d_out, int out_size)
{
    const float* x  = nullptr;
    const int*   am = nullptr;
    const float* Ws[4] = {nullptr, nullptr, nullptr, nullptr};
    const float* bs[4] = {nullptr, nullptr, nullptr, nullptr};
    int wi = 0, bi = 0;
    for (int i = 0; i < n_in; i++) {
        const long sz = in_sizes[i];
        if (sz == (long)Mtot * Dm)      x = (const float*)d_in[i];
        else if (sz == (long)Mtot)      am = (const int*)d_in[i];
        else if (sz == (long)Dm * Dm) { if (wi < 4) Ws[wi++] = (const float*)d_in[i]; }
        else if (sz == (long)Dm)      { if (bi < 4) bs[bi++] = (const float*)d_in[i]; }
    }

    __half *xf, *wf, *cf, *qf, *kf, *vf;
    cudaGetSymbolAddress((void**)&xf, g_xf);
    cudaGetSymbolAddress((void**)&wf, g_wf);
    cudaGetSymbolAddress((void**)&cf, g_cf);
    cudaGetSymbolAddress((void**)&qf, g_qf);
    cudaGetSymbolAddress((void**)&kf, g_kf);
    cudaGetSymbolAddress((void**)&vf, g_vf);

    cudaFuncSetAttribute(hmma_gemm_kernel<true>,
                         cudaFuncAttributeMaxDynamicSharedMemorySize, GEMM_SMEM);
    cudaFuncSetAttribute(hmma_gemm_kernel<false>,
                         cudaFuncAttributeMaxDynamicSharedMemorySize, GEMM_SMEM);
    cudaFuncSetAttribute(fa_hmma_kernel,
                         cudaFuncAttributeMaxDynamicSharedMemorySize, FA_SMEM);

    // Conversions
    const int n4x = Mtot * Dm / 4;
    const int n4w = Dm * Dm / 4;
    cvt_x_kernel<<<(n4x + 255) / 256, 256>>>(x, xf, n4x);
    cvt_w_kernel<<<dim3((n4w + 255) / 256, 4), 256>>>(
        Ws[0], Ws[1], Ws[2], Ws[3], wf);

    const size_t WSZ = (size_t)Dm * Dm;

    // Fused Q/K/V projections (single-pass fp16); Q carries 0.125*log2e.
    const float QSCALE = 0.125f * 1.4426950408889634f;
    const dim3 gqkv(Dm / 128, Mtot / 128, 3);
    hmma_gemm_kernel<true><<<gqkv, 256, GEMM_SMEM>>>(
        xf,
        wf + 0 * WSZ, wf + 1 * WSZ, wf + 2 * WSZ,
        bs[0], bs[1], bs[2],
        nullptr,
        qf, kf, vf,
        QSCALE);

    // Attention (round-13 config + alpha-skip, 4 CTAs/SM)
    const dim3 ga(Sq / 64, Hh, Bc);
    fa_hmma_kernel<<<ga, 128, FA_SMEM>>>(qf, kf, vf, am, cf);

    // Output projection (single-pass fp16)
    const dim3 gg(Dm / 128, Mtot / 128, 1);
    hmma_gemm_kernel<false><<<gg, 256, GEMM_SMEM>>>(
        cf,
        wf + 3 * WSZ, wf + 3 * WSZ, wf + 3 * WSZ,
        bs[3], bs[3], bs[3],
        (float*)d_out,
        nullptr, nullptr, nullptr,
        1.0f);
}

// round 16
// speedup vs baseline: 1.0674x; 1.0262x over previous
#include <cuda_runtime.h>
#include <cuda_fp16.h>
#include <math.h>
#include <stdint.h>

// Problem constants
constexpr int Bc  = 4;
constexpr int Sq  = 2048;
constexpr int Dm  = 1024;
constexpr int Hh  = 16;
constexpr int HDd = 64;
constexpr int Mtot = Bc * Sq;           // 8192

// Scratch (device globals: allocation-free per harness rules)
__device__ __half g_xf[(size_t)Mtot * Dm];            // x fp16
__device__ __half g_wf[(size_t)4 * Dm * Dm];          // W fp16
__device__ __half g_cf[(size_t)Mtot * Dm];            // ctx fp16
__device__ __half g_qf[(size_t)Mtot * Dm];            // Q fp16 (scale*log2e folded)
__device__ __half g_kf[(size_t)Mtot * Dm];            // K fp16
__device__ __half g_vf[(size_t)Mtot * Dm];            // V fp16

// ---------------------------------------------------------------------------
// PTX helpers
// ---------------------------------------------------------------------------
__device__ __forceinline__ uint32_t smem_u32(const void* p) {
    uint32_t a;
    asm("{ .reg .u64 t; cvta.to.shared.u64 t, %1; cvt.u32.u64 %0, t; }" : "=r"(a) : "l"(p));
    return a;
}
__device__ __forceinline__ void ldm_x4(uint32_t (&r)[4], uint32_t saddr) {
    asm volatile("ldmatrix.sync.aligned.m8n8.x4.shared.b16 {%0,%1,%2,%3}, [%4];"
        : "=r"(r[0]), "=r"(r[1]), "=r"(r[2]), "=r"(r[3]) : "r"(saddr));
}
__device__ __forceinline__ void ldm_x4_t(uint32_t (&r)[4], uint32_t saddr) {
    asm volatile("ldmatrix.sync.aligned.m8n8.x4.trans.shared.b16 {%0,%1,%2,%3}, [%4];"
        : "=r"(r[0]), "=r"(r[1]), "=r"(r[2]), "=r"(r[3]) : "r"(saddr));
}
__device__ __forceinline__ void mma_fp16(float (&c)[4], const uint32_t (&a)[4],
                                         uint32_t b0, uint32_t b1) {
    asm volatile("mma.sync.aligned.m16n8k16.row.col.f32.f16.f16.f32 "
        "{%0,%1,%2,%3}, {%4,%5,%6,%7}, {%8,%9}, {%0,%1,%2,%3};"
        : "+f"(c[0]), "+f"(c[1]), "+f"(c[2]), "+f"(c[3])
        : "r"(a[0]), "r"(a[1]), "r"(a[2]), "r"(a[3]), "r"(b0), "r"(b1));
}
__device__ __forceinline__ void cp16(uint32_t dst, const void* src) {
    asm volatile("cp.async.cg.shared.global [%0], [%1], 16;" :: "r"(dst), "l"(src) : "memory");
}
#define CP_COMMIT() asm volatile("cp.async.commit_group;" ::: "memory")
#define CP_WAIT(n)  asm volatile("cp.async.wait_group %0;" :: "n"(n) : "memory")

__device__ __forceinline__ uint32_t hf2(float a, float b) {
    __half2 t = __floats2half2_rn(a, b);
    return *reinterpret_cast<uint32_t*>(&t);
}
__device__ __forceinline__ uint32_t swz(int row, int chunk) {
    return (uint32_t)(row * 128 + ((chunk ^ (row & 7)) * 16));
}

// ---------------------------------------------------------------------------
// Conversions: x -> fp16; weights -> fp16 (y-indexed over 4 weights)
// ---------------------------------------------------------------------------
__global__ __launch_bounds__(256) void cvt_x_kernel(const float* __restrict__ in,
                                                    __half* __restrict__ out, int n4)
{
    const int i = blockIdx.x * blockDim.x + threadIdx.x;
    if (i >= n4) return;
    const float4 v = ((const float4*)in)[i];
    uint2 u;
    u.x = hf2(v.x, v.y);
    u.y = hf2(v.z, v.w);
    ((uint2*)out)[i] = u;
}

__global__ __launch_bounds__(256) void cvt_w_kernel(
    const float* __restrict__ w0, const float* __restrict__ w1,
    const float* __restrict__ w2, const float* __restrict__ w3,
    __half* __restrict__ outw)
{
    const int n4 = Dm * Dm / 4;
    const int i = blockIdx.x * blockDim.x + threadIdx.x;
    if (i >= n4) return;
    const int wsel = blockIdx.y;
    const float* in = wsel == 0 ? w0 : wsel == 1 ? w1 : wsel == 2 ? w2 : w3;
    const size_t off = (size_t)wsel * n4 + i;
    const float4 v = ((const float4*)in)[i];
    uint2 u;
    u.x = hf2(v.x, v.y);
    u.y = hf2(v.z, v.w);
    ((uint2*)outw)[off] = u;
}

// ---------------------------------------------------------------------------
// HMMA fp16 GEMM (single-pass): out[M,N] = A_fp16[M,K] @ W[N,K]^T + bias
// 128x128 CTA tile, BK=64, 8 warps (2x4), cp.async 3-stage ring (96KB).
// ---------------------------------------------------------------------------
constexpr int BKg = 64;
constexpr int NKC = Dm / BKg;                  // 16
constexpr int ATILE = 128 * 128;               // 16 KB
constexpr int STAGE_BYTES = 2 * ATILE;         // 32 KB (A + B)
constexpr int GEMM_SMEM = 3 * STAGE_BYTES;     // 96 KB

template <bool SPLIT>
__global__ __launch_bounds__(256, 2) void hmma_gemm_kernel(
    const __half* __restrict__ Af,
    const __half* __restrict__ B0, const __half* __restrict__ B1,
    const __half* __restrict__ B2,
    const float* __restrict__ bias0, const float* __restrict__ bias1,
    const float* __restrict__ bias2,
    float* __restrict__ outF,
    __half* __restrict__ oh0, __half* __restrict__ oh1,
    __half* __restrict__ oh2,
    float scale0)
{
    extern __shared__ char sm[];
    const uint32_t smb = smem_u32(sm);
    const int z    = blockIdx.z;
    const __half* Bw  = z == 0 ? B0 : z == 1 ? B1 : B2;
    const float* bias = z == 0 ? bias0 : z == 1 ? bias1 : bias2;
    __half* outH      = z == 0 ? oh0 : z == 1 ? oh1 : oh2;
    const float scale = (SPLIT && z == 0) ? scale0 : 1.0f;

    const int t    = threadIdx.x;
    const int wid  = t >> 5;
    const int lane = t & 31;
    const int m0   = blockIdx.y * 128;
    const int n0   = blockIdx.x * 128;
    const int wm   = (wid & 1) * 64;
    const int wn   = (wid >> 1) * 32;

    auto load_stage = [&](int s, int kc) {
        const uint32_t ab = smb + s * STAGE_BYTES;
        const uint32_t bb = ab + ATILE;
#pragma unroll
        for (int i = 0; i < 4; i++) {
            const int idx = t + i * 256;
            const int row = idx >> 3;
            const int c   = idx & 7;
            const int kofs = kc * BKg + c * 8;
            cp16(ab + swz(row, c), Af + (size_t)(m0 + row) * Dm + kofs);
            cp16(bb + swz(row, c), Bw + (size_t)(n0 + row) * Dm + kofs);
        }
        CP_COMMIT();
    };

    float acc[4][4][4];
#pragma unroll
    for (int i = 0; i < 4; i++)
#pragma unroll
        for (int j = 0; j < 4; j++)
#pragma unroll
            for (int r = 0; r < 4; r++) acc[i][j][r] = 0.0f;

    load_stage(0, 0);
    load_stage(1, 1);

    const int lrow = lane & 15;
    const int lsel = lane >> 4;

    int s = 0;
    for (int kc = 0; kc < NKC; kc++) {
        if (kc + 1 < NKC) { CP_WAIT(1); } else { CP_WAIT(0); }
        __syncthreads();
        if (kc + 2 < NKC) {
            int s2 = s + 2; if (s2 >= 3) s2 -= 3;
            load_stage(s2, kc + 2);
        }

        const uint32_t ab = smb + s * STAGE_BYTES;
        const uint32_t bb = ab + ATILE;

#pragma unroll
        for (int k16 = 0; k16 < 4; k16++) {
            const int ch = k16 * 2 + lsel;
            uint32_t a_f[4][4];
#pragma unroll
            for (int mt = 0; mt < 4; mt++)
                ldm_x4(a_f[mt], ab + swz(wm + mt * 16 + lrow, ch));
            uint32_t b_f[2][4];
#pragma unroll
            for (int nt = 0; nt < 2; nt++)
                ldm_x4(b_f[nt], bb + swz(wn + nt * 16 + lrow, ch));
#pragma unroll
            for (int mt = 0; mt < 4; mt++) {
#pragma unroll
                for (int n8 = 0; n8 < 4; n8++) {
                    const int nt = n8 >> 1, sl = n8 & 1;
                    mma_fp16(acc[mt][n8], a_f[mt], b_f[nt][sl], b_f[nt][sl + 2]);
                }
            }
        }
        if (++s == 3) s = 0;
    }

#pragma unroll
    for (int mt = 0; mt < 4; mt++) {
#pragma unroll
        for (int n8 = 0; n8 < 4; n8++) {
            const int r0 = m0 + wm + mt * 16 + (lane >> 2);
            const int c0 = n0 + wn + n8 * 8 + (lane & 3) * 2;
#pragma unroll
            for (int half = 0; half < 2; half++) {
                const int m = r0 + half * 8;
                const int b_ = m / Sq;
                const int s_ = m % Sq;
                const float v0 = (acc[mt][n8][half * 2 + 0] + bias[c0]) * scale;
                const float v1 = (acc[mt][n8][half * 2 + 1] + bias[c0 + 1]) * scale;
                if (SPLIT) {
                    const int h_ = c0 >> 6;
                    const int d_ = c0 & 63;
                    const size_t off =
                        ((((size_t)(b_ * Hh + h_)) * Sq + s_) * HDd + d_) >> 1;
                    ((uint32_t*)outH)[off] = hf2(v0, v1);
                } else {
                    float* dst = outF + (size_t)m * Dm + c0;
                    dst[0] = v0; dst[1] = v1;
                }
            }
        }
    }
}

// ---------------------------------------------------------------------------
// HMMA fp16 flash attention (round-13 numerics): CTA = (64 queries, head,
// batch), 4 warps. Q fp16 (8KB), K+V fp16 double-buffered (2x16KB),
// mask 2x256B -> 41KB/CTA, 4 CTAs/SM. Full fragment buffers for ILP.
// SINGLE barrier per K-tile: CP_WAIT(0); sync; load(next); compute(cur).
// Base-2 softmax; pad mask via ballot. Longest-first CTA order.
// ---------------------------------------------------------------------------
constexpr int FA_Q    = 8192;
constexpr int FA_KVST = 16384;                 // K 8KB + V 8KB
constexpr int FA_MOFF = FA_Q + 2 * FA_KVST;    // 40960
constexpr int FA_SMEM = FA_MOFF + 512;         // 41472

__global__ __launch_bounds__(128, 4) void fa_hmma_kernel(
    const __half* __restrict__ Qf,
    const __half* __restrict__ Kf,
    const __half* __restrict__ Vf,
    const int* __restrict__ maskg,
    __half* __restrict__ Cf)
{
    extern __shared__ char sm[];
    const uint32_t smb = smem_u32(sm);
    const int t    = threadIdx.x;
    const int w    = t >> 5;
    const int lane = t & 31;
    const int qt   = gridDim.x - 1 - blockIdx.x;   // longest-first
    const int h    = blockIdx.y;
    const int b    = blockIdx.z;
    const size_t hb = ((size_t)(b * Hh + h)) * Sq * HDd;

    const uint32_t qfb = smb;

    auto load_kv = [&](int s, int kt2) {
        const uint32_t kb = smb + FA_Q + s * FA_KVST;
        const char* sK = (const char*)(Kf + hb + (size_t)kt2 * 64 * HDd);
        const char* sV = (const char*)(Vf + hb + (size_t)kt2 * 64 * HDd);
#pragma unroll
        for (int i = 0; i < 4; i++) {
            const int idx = t + i * 128;
            const int row = idx >> 3, c = idx & 7;
            cp16(kb + swz(row, c), sK + idx * 16);
            cp16(kb + 8192 + swz(row, c), sV + idx * 16);
        }
        if (t < 16) cp16(smb + FA_MOFF + s * 256 + t * 16,
                         maskg + b * Sq + kt2 * 64 + t * 4);
        CP_COMMIT();
    };

    // Prologue: Q tile + K/V(0) + mask(0) in one group.
    {
        const char* srcQ = (const char*)(Qf + hb + (size_t)qt * 64 * HDd);
#pragma unroll
        for (int i = 0; i < 4; i++) {
            const int idx = t + i * 128;
            const int row = idx >> 3, c = idx & 7;
            cp16(qfb + swz(row, c), srcQ + idx * 16);
        }
    }
    load_kv(0, 0);

    const int lrow  = lane & 15;
    const int lsel  = lane >> 4;
    const int rl    = lane >> 2;
    const int cbase = (lane & 3) * 2;
    const int wr0   = w * 16;

    float m_i[2] = {-INFINITY, -INFINITY};
    float l_i[2] = {0.0f, 0.0f};
    float o[8][4];
#pragma unroll
    for (int n8 = 0; n8 < 8; n8++)
#pragma unroll
        for (int c = 0; c < 4; c++) o[n8][c] = 0.0f;

    for (int kt2 = 0; kt2 <= qt; kt2++) {
        const int s = kt2 & 1;

        // Single barrier per tile: retire this warp's pending loads (stage s
        // data), publish to all warps; the barrier also guarantees everyone
        // finished reading stage s^1 (used in iter kt2-1) before we reload it.
        CP_WAIT(0);
        __syncthreads();
        if (kt2 < qt) load_kv(s ^ 1, kt2 + 1);   // lands under compute below

        const uint32_t kfb = smb + FA_Q + s * FA_KVST;
        const uint32_t vfb = kfb + 8192;
        const int* msk = (const int*)(sm + FA_MOFF + s * 256);

        // ---- S = Q @ K^T (single pass; scores pre-scaled by 0.125*log2e) ----
        float sc[8][4];
#pragma unroll
        for (int n8 = 0; n8 < 8; n8++)
#pragma unroll
            for (int c = 0; c < 4; c++) sc[n8][c] = 0.0f;

#pragma unroll
        for (int k16 = 0; k16 < 4; k16++) {
            const int ch = k16 * 2 + lsel;
            uint32_t qf[4];
            ldm_x4(qf, qfb + swz(wr0 + lrow, ch));
            uint32_t kf[4][4];
#pragma unroll
            for (int nt = 0; nt < 4; nt++)
                ldm_x4(kf[nt], kfb + swz(nt * 16 + lrow, ch));
#pragma unroll
            for (int n8 = 0; n8 < 8; n8++) {
                const int nt = n8 >> 1, sl = n8 & 1;
                mma_fp16(sc[n8], qf, kf[nt][sl], kf[nt][sl + 2]);
            }
        }

        // ---- masking: causal on diagonal; pad via ballot bitmask ----
        if (kt2 == qt) {
            const int qi0 = qt * 64 + wr0 + rl;
#pragma unroll
            for (int n8 = 0; n8 < 8; n8++) {
#pragma unroll
                for (int c = 0; c < 4; c++) {
                    const int kj = kt2 * 64 + n8 * 8 + cbase + (c & 1);
                    const int qi = qi0 + (c >> 1) * 8;
                    if (kj > qi) sc[n8][c] = -INFINITY;
                }
            }
        }
        const uint32_t bm0 = __ballot_sync(0xffffffffu, msk[lane] != 0);
        const uint32_t bm1 = __ballot_sync(0xffffffffu, msk[lane + 32] != 0);
        if ((bm0 & bm1) != 0xffffffffu) {
#pragma unroll
            for (int n8 = 0; n8 < 8; n8++) {
#pragma unroll
                for (int c = 0; c < 4; c++) {
                    const int colL = n8 * 8 + cbase + (c & 1);
                    const uint32_t bit =
                        (colL < 32 ? bm0 >> colL : bm1 >> (colL - 32)) & 1u;
                    if (!bit) sc[n8][c] = -1e9f;
                }
            }
        }

        // ---- online softmax in base-2 (rows rl, rl+8) ----
#pragma unroll
        for (int r = 0; r < 2; r++) {
            float mx = -INFINITY;
#pragma unroll
            for (int n8 = 0; n8 < 8; n8++)
                mx = fmaxf(mx, fmaxf(sc[n8][2 * r], sc[n8][2 * r + 1]));
            mx = fmaxf(mx, __shfl_xor_sync(0xffffffffu, mx, 1));
            mx = fmaxf(mx, __shfl_xor_sync(0xffffffffu, mx, 2));
            const float mnew  = fmaxf(m_i[r], mx);
            const float alpha = exp2f(m_i[r] - mnew);
            float sum = 0.0f;
#pragma unroll
            for (int n8 = 0; n8 < 8; n8++) {
                const float p0 = exp2f(sc[n8][2 * r]     - mnew);
                const float p1 = exp2f(sc[n8][2 * r + 1] - mnew);
                sc[n8][2 * r] = p0; sc[n8][2 * r + 1] = p1;
                sum += p0 + p1;
            }
            sum += __shfl_xor_sync(0xffffffffu, sum, 1);
            sum += __shfl_xor_sync(0xffffffffu, sum, 2);
            l_i[r] = l_i[r] * alpha + sum;
            m_i[r] = mnew;
#pragma unroll
            for (int n8 = 0; n8 < 8; n8++) {
                o[n8][2 * r] *= alpha; o[n8][2 * r + 1] *= alpha;
            }
        }

        // ---- P -> single fp16 A-fragments ----
        uint32_t pa[4][4];
#pragma unroll
        for (int j = 0; j < 4; j++) {
#pragma unroll
            for (int u = 0; u < 4; u++) {
                const int tile = 2 * j + (u >> 1);
                const int ci   = (u & 1) * 2;
                pa[j][u] = hf2(sc[tile][ci], sc[tile][ci + 1]);
            }
        }

        // ---- O += P @ V (single pass) ----
#pragma unroll
        for (int j = 0; j < 4; j++) {
            const int mrow = 16 * j + ((lane >> 3) & 1) * 8 + (lane & 7);
            uint32_t vf[4][4];
#pragma unroll
            for (int hp = 0; hp < 4; hp++) {
                const int chv = hp * 2 + (lane >> 4);
                ldm_x4_t(vf[hp], vfb + swz(mrow, chv));
            }
#pragma unroll
            for (int n8 = 0; n8 < 8; n8++) {
                const int hp = n8 >> 1, q_ = n8 & 1;
                mma_fp16(o[n8], pa[j], vf[hp][2 * q_], vf[hp][2 * q_ + 1]);
            }
        }
    }

    // ---- normalize + write ctx fp16 [B,S,D] ----
#pragma unroll
    for (int r = 0; r < 2; r++) {
        const float inv = 1.0f / l_i[r];
        const int m = qt * 64 + wr0 + rl + r * 8;
        const size_t rowoff = ((size_t)b * Sq + m) * Dm + h * HDd;
#pragma unroll
        for (int n8 = 0; n8 < 8; n8++) {
            const int col = n8 * 8 + cbase;
            *((uint32_t*)(Cf + rowoff + col)) =
                hf2(o[n8][2 * r] * inv, o[n8][2 * r + 1] * inv);
        }
    }
}

// ---------------------------------------------------------------------------
// Launch
// ---------------------------------------------------------------------------
extern "C" void kernel_launch(void* const* d_in, const int* in_sizes, int n_in,
                              void* d_out, int out_size)
{
    const float* x  = nullptr;
    const int*   am = nullptr;
    const float* Ws[4] = {nullptr, nullptr, nullptr, nullptr};
    const float* bs[4] = {nullptr, nullptr, nullptr, nullptr};
    int wi = 0, bi = 0;
    for (int i = 0; i < n_in; i++) {
        const long sz = in_sizes[i];
        if (sz == (long)Mtot * Dm)      x = (const float*)d_in[i];
        else if (sz == (long)Mtot)      am = (const int*)d_in[i];
        else if (sz == (long)Dm * Dm) { if (wi < 4) Ws[wi++] = (const float*)d_in[i]; }
        else if (sz == (long)Dm)      { if (bi < 4) bs[bi++] = (const float*)d_in[i]; }
    }

    __half *xf, *wf, *cf, *qf, *kf, *vf;
    cudaGetSymbolAddress((void**)&xf, g_xf);
    cudaGetSymbolAddress((void**)&wf, g_wf);
    cudaGetSymbolAddress((void**)&cf, g_cf);
    cudaGetSymbolAddress((void**)&qf, g_qf);
    cudaGetSymbolAddress((void**)&kf, g_kf);
    cudaGetSymbolAddress((void**)&vf, g_vf);

    cudaFuncSetAttribute(hmma_gemm_kernel<true>,
                         cudaFuncAttributeMaxDynamicSharedMemorySize, GEMM_SMEM);
    cudaFuncSetAttribute(hmma_gemm_kernel<false>,
                         cudaFuncAttributeMaxDynamicSharedMemorySize, GEMM_SMEM);
    cudaFuncSetAttribute(fa_hmma_kernel,
                         cudaFuncAttributeMaxDynamicSharedMemorySize, FA_SMEM);

    // Conversions
    const int n4x = Mtot * Dm / 4;
    const int n4w = Dm * Dm / 4;
    cvt_x_kernel<<<(n4x + 255) / 256, 256>>>(x, xf, n4x);
    cvt_w_kernel<<<dim3((n4w + 255) / 256, 4), 256>>>(
        Ws[0], Ws[1], Ws[2], Ws[3], wf);

    const size_t WSZ = (size_t)Dm * Dm;

    // Fused Q/K/V projections (single-pass fp16); Q carries 0.125*log2e.
    const float QSCALE = 0.125f * 1.4426950408889634f;
    const dim3 gqkv(Dm / 128, Mtot / 128, 3);
    hmma_gemm_kernel<true><<<gqkv, 256, GEMM_SMEM>>>(
        xf,
        wf + 0 * WSZ, wf + 1 * WSZ, wf + 2 * WSZ,
        bs[0], bs[1], bs[2],
        nullptr,
        qf, kf, vf,
        QSCALE);

    // Attention (round-13 numerics, single-barrier pipeline, 4 CTAs/SM)
    const dim3 ga(Sq / 64, Hh, Bc);
    fa_hmma_kernel<<<ga, 128, FA_SMEM>>>(qf, kf, vf, am, cf);

    // Output projection (single-pass fp16)
    const dim3 gg(Dm / 128, Mtot / 128, 1);
    hmma_gemm_kernel<false><<<gg, 256, GEMM_SMEM>>>(
        cf,
        wf + 3 * WSZ, wf + 3 * WSZ, wf + 3 * WSZ,
        bs[3], bs[3], bs[3],
        (float*)d_out,
        nullptr, nullptr, nullptr,
        1.0f);
}

// round 17
// speedup vs baseline: 1.0744x; 1.0065x over previous
#include <cuda_runtime.h>
#include <cuda_fp16.h>
#include <math.h>
#include <stdint.h>

// Problem constants
constexpr int Bc  = 4;
constexpr int Sq  = 2048;
constexpr int Dm  = 1024;
constexpr int Hh  = 16;
constexpr int HDd = 64;
constexpr int Mtot = Bc * Sq;           // 8192

// Scratch (device globals: allocation-free per harness rules)
__device__ __half g_xf[(size_t)Mtot * Dm];            // x fp16
__device__ __half g_wf[(size_t)4 * Dm * Dm];          // W fp16
__device__ __half g_cf[(size_t)Mtot * Dm];            // ctx fp16
__device__ __half g_qf[(size_t)Mtot * Dm];            // Q fp16 (scale*log2e folded)
__device__ __half g_kf[(size_t)Mtot * Dm];            // K fp16
__device__ __half g_vf[(size_t)Mtot * Dm];            // V fp16

// ---------------------------------------------------------------------------
// PTX helpers
// ---------------------------------------------------------------------------
__device__ __forceinline__ uint32_t smem_u32(const void* p) {
    uint32_t a;
    asm("{ .reg .u64 t; cvta.to.shared.u64 t, %1; cvt.u32.u64 %0, t; }" : "=r"(a) : "l"(p));
    return a;
}
__device__ __forceinline__ void ldm_x4(uint32_t (&r)[4], uint32_t saddr) {
    asm volatile("ldmatrix.sync.aligned.m8n8.x4.shared.b16 {%0,%1,%2,%3}, [%4];"
        : "=r"(r[0]), "=r"(r[1]), "=r"(r[2]), "=r"(r[3]) : "r"(saddr));
}
__device__ __forceinline__ void ldm_x4_t(uint32_t (&r)[4], uint32_t saddr) {
    asm volatile("ldmatrix.sync.aligned.m8n8.x4.trans.shared.b16 {%0,%1,%2,%3}, [%4];"
        : "=r"(r[0]), "=r"(r[1]), "=r"(r[2]), "=r"(r[3]) : "r"(saddr));
}
__device__ __forceinline__ void mma_fp16(float (&c)[4], const uint32_t (&a)[4],
                                         uint32_t b0, uint32_t b1) {
    asm volatile("mma.sync.aligned.m16n8k16.row.col.f32.f16.f16.f32 "
        "{%0,%1,%2,%3}, {%4,%5,%6,%7}, {%8,%9}, {%0,%1,%2,%3};"
        : "+f"(c[0]), "+f"(c[1]), "+f"(c[2]), "+f"(c[3])
        : "r"(a[0]), "r"(a[1]), "r"(a[2]), "r"(a[3]), "r"(b0), "r"(b1));
}
__device__ __forceinline__ void cp16(uint32_t dst, const void* src) {
    asm volatile("cp.async.cg.shared.global [%0], [%1], 16;" :: "r"(dst), "l"(src) : "memory");
}
#define CP_COMMIT() asm volatile("cp.async.commit_group;" ::: "memory")
#define CP_WAIT(n)  asm volatile("cp.async.wait_group %0;" :: "n"(n) : "memory")

__device__ __forceinline__ uint32_t hf2(float a, float b) {
    __half2 t = __floats2half2_rn(a, b);
    return *reinterpret_cast<uint32_t*>(&t);
}
__device__ __forceinline__ uint32_t swz(int row, int chunk) {
    return (uint32_t)(row * 128 + ((chunk ^ (row & 7)) * 16));
}

// ---------------------------------------------------------------------------
// Conversions: x -> fp16; weights -> fp16 (y-indexed over 4 weights)
// ---------------------------------------------------------------------------
__global__ __launch_bounds__(256) void cvt_x_kernel(const float* __restrict__ in,
                                                    __half* __restrict__ out, int n4)
{
    const int i = blockIdx.x * blockDim.x + threadIdx.x;
    if (i >= n4) return;
    const float4 v = ((const float4*)in)[i];
    uint2 u;
    u.x = hf2(v.x, v.y);
    u.y = hf2(v.z, v.w);
    ((uint2*)out)[i] = u;
}

__global__ __launch_bounds__(256) void cvt_w_kernel(
    const float* __restrict__ w0, const float* __restrict__ w1,
    const float* __restrict__ w2, const float* __restrict__ w3,
    __half* __restrict__ outw)
{
    const int n4 = Dm * Dm / 4;
    const int i = blockIdx.x * blockDim.x + threadIdx.x;
    if (i >= n4) return;
    const int wsel = blockIdx.y;
    const float* in = wsel == 0 ? w0 : wsel == 1 ? w1 : wsel == 2 ? w2 : w3;
    const size_t off = (size_t)wsel * n4 + i;
    const float4 v = ((const float4*)in)[i];
    uint2 u;
    u.x = hf2(v.x, v.y);
    u.y = hf2(v.z, v.w);
    ((uint2*)outw)[off] = u;
}

// ---------------------------------------------------------------------------
// HMMA fp16 GEMM (single-pass): out[M,N] = A_fp16[M,K] @ W[N,K]^T + bias
// 128x128 CTA tile, BK=64, 8 warps (2x4), cp.async 3-stage ring (96KB).
// ---------------------------------------------------------------------------
constexpr int BKg = 64;
constexpr int NKC = Dm / BKg;                  // 16
constexpr int ATILE = 128 * 128;               // 16 KB
constexpr int STAGE_BYTES = 2 * ATILE;         // 32 KB (A + B)
constexpr int GEMM_SMEM = 3 * STAGE_BYTES;     // 96 KB

template <bool SPLIT>
__global__ __launch_bounds__(256, 2) void hmma_gemm_kernel(
    const __half* __restrict__ Af,
    const __half* __restrict__ B0, const __half* __restrict__ B1,
    const __half* __restrict__ B2,
    const float* __restrict__ bias0, const float* __restrict__ bias1,
    const float* __restrict__ bias2,
    float* __restrict__ outF,
    __half* __restrict__ oh0, __half* __restrict__ oh1,
    __half* __restrict__ oh2,
    float scale0)
{
    extern __shared__ char sm[];
    const uint32_t smb = smem_u32(sm);
    const int z    = blockIdx.z;
    const __half* Bw  = z == 0 ? B0 : z == 1 ? B1 : B2;
    const float* bias = z == 0 ? bias0 : z == 1 ? bias1 : bias2;
    __half* outH      = z == 0 ? oh0 : z == 1 ? oh1 : oh2;
    const float scale = (SPLIT && z == 0) ? scale0 : 1.0f;

    const int t    = threadIdx.x;
    const int wid  = t >> 5;
    const int lane = t & 31;
    const int m0   = blockIdx.y * 128;
    const int n0   = blockIdx.x * 128;
    const int wm   = (wid & 1) * 64;
    const int wn   = (wid >> 1) * 32;

    auto load_stage = [&](int s, int kc) {
        const uint32_t ab = smb + s * STAGE_BYTES;
        const uint32_t bb = ab + ATILE;
#pragma unroll
        for (int i = 0; i < 4; i++) {
            const int idx = t + i * 256;
            const int row = idx >> 3;
            const int c   = idx & 7;
            const int kofs = kc * BKg + c * 8;
            cp16(ab + swz(row, c), Af + (size_t)(m0 + row) * Dm + kofs);
            cp16(bb + swz(row, c), Bw + (size_t)(n0 + row) * Dm + kofs);
        }
        CP_COMMIT();
    };

    float acc[4][4][4];
#pragma unroll
    for (int i = 0; i < 4; i++)
#pragma unroll
        for (int j = 0; j < 4; j++)
#pragma unroll
            for (int r = 0; r < 4; r++) acc[i][j][r] = 0.0f;

    load_stage(0, 0);
    load_stage(1, 1);

    const int lrow = lane & 15;
    const int lsel = lane >> 4;

    int s = 0;
    for (int kc = 0; kc < NKC; kc++) {
        if (kc + 1 < NKC) { CP_WAIT(1); } else { CP_WAIT(0); }
        __syncthreads();
        if (kc + 2 < NKC) {
            int s2 = s + 2; if (s2 >= 3) s2 -= 3;
            load_stage(s2, kc + 2);
        }

        const uint32_t ab = smb + s * STAGE_BYTES;
        const uint32_t bb = ab + ATILE;

#pragma unroll
        for (int k16 = 0; k16 < 4; k16++) {
            const int ch = k16 * 2 + lsel;
            uint32_t a_f[4][4];
#pragma unroll
            for (int mt = 0; mt < 4; mt++)
                ldm_x4(a_f[mt], ab + swz(wm + mt * 16 + lrow, ch));
            uint32_t b_f[2][4];
#pragma unroll
            for (int nt = 0; nt < 2; nt++)
                ldm_x4(b_f[nt], bb + swz(wn + nt * 16 + lrow, ch));
#pragma unroll
            for (int mt = 0; mt < 4; mt++) {
#pragma unroll
                for (int n8 = 0; n8 < 4; n8++) {
                    const int nt = n8 >> 1, sl = n8 & 1;
                    mma_fp16(acc[mt][n8], a_f[mt], b_f[nt][sl], b_f[nt][sl + 2]);
                }
            }
        }
        if (++s == 3) s = 0;
    }

#pragma unroll
    for (int mt = 0; mt < 4; mt++) {
#pragma unroll
        for (int n8 = 0; n8 < 4; n8++) {
            const int r0 = m0 + wm + mt * 16 + (lane >> 2);
            const int c0 = n0 + wn + n8 * 8 + (lane & 3) * 2;
#pragma unroll
            for (int half = 0; half < 2; half++) {
                const int m = r0 + half * 8;
                const int b_ = m / Sq;
                const int s_ = m % Sq;
                const float v0 = (acc[mt][n8][half * 2 + 0] + bias[c0]) * scale;
                const float v1 = (acc[mt][n8][half * 2 + 1] + bias[c0 + 1]) * scale;
                if (SPLIT) {
                    const int h_ = c0 >> 6;
                    const int d_ = c0 & 63;
                    const size_t off =
                        ((((size_t)(b_ * Hh + h_)) * Sq + s_) * HDd + d_) >> 1;
                    ((uint32_t*)outH)[off] = hf2(v0, v1);
                } else {
                    float* dst = outF + (size_t)m * Dm + c0;
                    dst[0] = v0; dst[1] = v1;
                }
            }
        }
    }
}

// ---------------------------------------------------------------------------
// HMMA fp16 flash attention: CTA = (64 queries, head, batch), 4 warps.
// Q fp16 (8KB), K+V fp16 double-buffered (2x16KB), mask 2x256B -> 41KB/CTA,
// 4 CTAs/SM. Single barrier per tile; mainloop manually unrolled x2 with
// static stage addresses. Tree reductions in softmax. Base-2 softmax.
// Longest-first: qt = gridDim.x - 1 - blockIdx.x.
// ---------------------------------------------------------------------------
constexpr int FA_Q    = 8192;
constexpr int FA_KVST = 16384;                 // K 8KB + V 8KB
constexpr int FA_MOFF = FA_Q + 2 * FA_KVST;    // 40960
constexpr int FA_SMEM = FA_MOFF + 512;         // 41472

__global__ __launch_bounds__(128, 4) void fa_hmma_kernel(
    const __half* __restrict__ Qf,
    const __half* __restrict__ Kf,
    const __half* __restrict__ Vf,
    const int* __restrict__ maskg,
    __half* __restrict__ Cf)
{
    extern __shared__ char sm[];
    const uint32_t smb = smem_u32(sm);
    const int t    = threadIdx.x;
    const int w    = t >> 5;
    const int lane = t & 31;
    const int qt   = gridDim.x - 1 - blockIdx.x;   // longest-first
    const int h    = blockIdx.y;
    const int b    = blockIdx.z;
    const size_t hb = ((size_t)(b * Hh + h)) * Sq * HDd;

    const uint32_t qfb = smb;

    auto load_kv = [&](int s, int kt2) {
        const uint32_t kb = smb + FA_Q + s * FA_KVST;
        const char* sK = (const char*)(Kf + hb + (size_t)kt2 * 64 * HDd);
        const char* sV = (const char*)(Vf + hb + (size_t)kt2 * 64 * HDd);
#pragma unroll
        for (int i = 0; i < 4; i++) {
            const int idx = t + i * 128;
            const int row = idx >> 3, c = idx & 7;
            cp16(kb + swz(row, c), sK + idx * 16);
            cp16(kb + 8192 + swz(row, c), sV + idx * 16);
        }
        if (t < 16) cp16(smb + FA_MOFF + s * 256 + t * 16,
                         maskg + b * Sq + kt2 * 64 + t * 4);
        CP_COMMIT();
    };

    // Prologue: Q tile + K/V(0) + mask(0) in one group.
    {
        const char* srcQ = (const char*)(Qf + hb + (size_t)qt * 64 * HDd);
#pragma unroll
        for (int i = 0; i < 4; i++) {
            const int idx = t + i * 128;
            const int row = idx >> 3, c = idx & 7;
            cp16(qfb + swz(row, c), srcQ + idx * 16);
        }
    }
    load_kv(0, 0);

    const int lrow  = lane & 15;
    const int lsel  = lane >> 4;
    const int rl    = lane >> 2;
    const int cbase = (lane & 3) * 2;
    const int wr0   = w * 16;

    float m_i[2] = {-INFINITY, -INFINITY};
    float l_i[2] = {0.0f, 0.0f};
    float o[8][4];
#pragma unroll
    for (int n8 = 0; n8 < 8; n8++)
#pragma unroll
        for (int c = 0; c < 4; c++) o[n8][c] = 0.0f;

    // One K-tile, compile-time stage base addresses.
    auto compute_tile = [&](int kt2, uint32_t kfb, uint32_t vfb, const int* msk) {
        // ---- S = Q @ K^T (scores pre-scaled by 0.125*log2e) ----
        float sc[8][4];
#pragma unroll
        for (int n8 = 0; n8 < 8; n8++)
#pragma unroll
            for (int c = 0; c < 4; c++) sc[n8][c] = 0.0f;

#pragma unroll
        for (int k16 = 0; k16 < 4; k16++) {
            const int ch = k16 * 2 + lsel;
            uint32_t qf[4];
            ldm_x4(qf, qfb + swz(wr0 + lrow, ch));
            uint32_t kf[4][4];
#pragma unroll
            for (int nt = 0; nt < 4; nt++)
                ldm_x4(kf[nt], kfb + swz(nt * 16 + lrow, ch));
#pragma unroll
            for (int n8 = 0; n8 < 8; n8++) {
                const int nt = n8 >> 1, sl = n8 & 1;
                mma_fp16(sc[n8], qf, kf[nt][sl], kf[nt][sl + 2]);
            }
        }

        // ---- masking: causal on diagonal; pad via ballot bitmask ----
        if (kt2 == qt) {
            const int qi0 = qt * 64 + wr0 + rl;
#pragma unroll
            for (int n8 = 0; n8 < 8; n8++) {
#pragma unroll
                for (int c = 0; c < 4; c++) {
                    const int kj = kt2 * 64 + n8 * 8 + cbase + (c & 1);
                    const int qi = qi0 + (c >> 1) * 8;
                    if (kj > qi) sc[n8][c] = -INFINITY;
                }
            }
        }
        const uint32_t bm0 = __ballot_sync(0xffffffffu, msk[lane] != 0);
        const uint32_t bm1 = __ballot_sync(0xffffffffu, msk[lane + 32] != 0);
        if ((bm0 & bm1) != 0xffffffffu) {
#pragma unroll
            for (int n8 = 0; n8 < 8; n8++) {
#pragma unroll
                for (int c = 0; c < 4; c++) {
                    const int colL = n8 * 8 + cbase + (c & 1);
                    const uint32_t bit =
                        (colL < 32 ? bm0 >> colL : bm1 >> (colL - 32)) & 1u;
                    if (!bit) sc[n8][c] = -1e9f;
                }
            }
        }

        // ---- online softmax in base-2 (rows rl, rl+8); tree reductions ----
#pragma unroll
        for (int r = 0; r < 2; r++) {
            // balanced max tree over 16 values
            float pm[8];
#pragma unroll
            for (int n8 = 0; n8 < 8; n8++)
                pm[n8] = fmaxf(sc[n8][2 * r], sc[n8][2 * r + 1]);
            const float m01 = fmaxf(pm[0], pm[1]);
            const float m23 = fmaxf(pm[2], pm[3]);
            const float m45 = fmaxf(pm[4], pm[5]);
            const float m67 = fmaxf(pm[6], pm[7]);
            float mx = fmaxf(fmaxf(m01, m23), fmaxf(m45, m67));
            mx = fmaxf(mx, __shfl_xor_sync(0xffffffffu, mx, 1));
            mx = fmaxf(mx, __shfl_xor_sync(0xffffffffu, mx, 2));
            const float mnew  = fmaxf(m_i[r], mx);
            const float alpha = exp2f(m_i[r] - mnew);
            // exp + balanced sum tree
            float ps[8];
#pragma unroll
            for (int n8 = 0; n8 < 8; n8++) {
                const float p0 = exp2f(sc[n8][2 * r]     - mnew);
                const float p1 = exp2f(sc[n8][2 * r + 1] - mnew);
                sc[n8][2 * r] = p0; sc[n8][2 * r + 1] = p1;
                ps[n8] = p0 + p1;
            }
            const float s01 = ps[0] + ps[1];
            const float s23 = ps[2] + ps[3];
            const float s45 = ps[4] + ps[5];
            const float s67 = ps[6] + ps[7];
            float sum = (s01 + s23) + (s45 + s67);
            sum += __shfl_xor_sync(0xffffffffu, sum, 1);
            sum += __shfl_xor_sync(0xffffffffu, sum, 2);
            l_i[r] = l_i[r] * alpha + sum;
            m_i[r] = mnew;
#pragma unroll
            for (int n8 = 0; n8 < 8; n8++) {
                o[n8][2 * r] *= alpha; o[n8][2 * r + 1] *= alpha;
            }
        }

        // ---- P -> single fp16 A-fragments ----
        uint32_t pa[4][4];
#pragma unroll
        for (int j = 0; j < 4; j++) {
#pragma unroll
            for (int u = 0; u < 4; u++) {
                const int tile = 2 * j + (u >> 1);
                const int ci   = (u & 1) * 2;
                pa[j][u] = hf2(sc[tile][ci], sc[tile][ci + 1]);
            }
        }

        // ---- O += P @ V ----
#pragma unroll
        for (int j = 0; j < 4; j++) {
            const int mrow = 16 * j + ((lane >> 3) & 1) * 8 + (lane & 7);
            uint32_t vf[4][4];
#pragma unroll
            for (int hp = 0; hp < 4; hp++) {
                const int chv = hp * 2 + (lane >> 4);
                ldm_x4_t(vf[hp], vfb + swz(mrow, chv));
            }
#pragma unroll
            for (int n8 = 0; n8 < 8; n8++) {
                const int hp = n8 >> 1, q_ = n8 & 1;
                mma_fp16(o[n8], pa[j], vf[hp][2 * q_], vf[hp][2 * q_ + 1]);
            }
        }
    };

    // Mainloop unrolled x2 with static stage bases.
    const uint32_t k0b = smb + FA_Q;
    const uint32_t v0b = k0b + 8192;
    const uint32_t k1b = smb + FA_Q + FA_KVST;
    const uint32_t v1b = k1b + 8192;
    const int* m0p = (const int*)(sm + FA_MOFF);
    const int* m1p = (const int*)(sm + FA_MOFF + 256);

    int kt2 = 0;
    for (;;) {
        // even tile -> stage 0
        CP_WAIT(0);
        __syncthreads();
        if (kt2 < qt) load_kv(1, kt2 + 1);
        compute_tile(kt2, k0b, v0b, m0p);
        if (kt2 == qt) break;
        kt2++;
        // odd tile -> stage 1
        CP_WAIT(0);
        __syncthreads();
        if (kt2 < qt) load_kv(0, kt2 + 1);
        compute_tile(kt2, k1b, v1b, m1p);
        if (kt2 == qt) break;
        kt2++;
    }

    // ---- normalize + write ctx fp16 [B,S,D] ----
#pragma unroll
    for (int r = 0; r < 2; r++) {
        const float inv = 1.0f / l_i[r];
        const int m = qt * 64 + wr0 + rl + r * 8;
        const size_t rowoff = ((size_t)b * Sq + m) * Dm + h * HDd;
#pragma unroll
        for (int n8 = 0; n8 < 8; n8++) {
            const int col = n8 * 8 + cbase;
            *((uint32_t*)(Cf + rowoff + col)) =
                hf2(o[n8][2 * r] * inv, o[n8][2 * r + 1] * inv);
        }
    }
}

// ---------------------------------------------------------------------------
// Launch
// ---------------------------------------------------------------------------
extern "C" void kernel_launch(void* const* d_in, const int* in_sizes, int n_in,
                              void* d_out, int out_size)
{
    const float* x  = nullptr;
    const int*   am = nullptr;
    const float* Ws[4] = {nullptr, nullptr, nullptr, nullptr};
    const float* bs[4] = {nullptr, nullptr, nullptr, nullptr};
    int wi = 0, bi = 0;
    for (int i = 0; i < n_in; i++) {
        const long sz = in_sizes[i];
        if (sz == (long)Mtot * Dm)      x = (const float*)d_in[i];
        else if (sz == (long)Mtot)      am = (const int*)d_in[i];
        else if (sz == (long)Dm * Dm) { if (wi < 4) Ws[wi++] = (const float*)d_in[i]; }
        else if (sz == (long)Dm)      { if (bi < 4) bs[bi++] = (const float*)d_in[i]; }
    }

    __half *xf, *wf, *cf, *qf, *kf, *vf;
    cudaGetSymbolAddress((void**)&xf, g_xf);
    cudaGetSymbolAddress((void**)&wf, g_wf);
    cudaGetSymbolAddress((void**)&cf, g_cf);
    cudaGetSymbolAddress((void**)&qf, g_qf);
    cudaGetSymbolAddress((void**)&kf, g_kf);
    cudaGetSymbolAddress((void**)&vf, g_vf);

    cudaFuncSetAttribute(hmma_gemm_kernel<true>,
                         cudaFuncAttributeMaxDynamicSharedMemorySize, GEMM_SMEM);
    cudaFuncSetAttribute(hmma_gemm_kernel<false>,
                         cudaFuncAttributeMaxDynamicSharedMemorySize, GEMM_SMEM);
    cudaFuncSetAttribute(fa_hmma_kernel,
                         cudaFuncAttributeMaxDynamicSharedMemorySize, FA_SMEM);

    // Conversions
    const int n4x = Mtot * Dm / 4;
    const int n4w = Dm * Dm / 4;
    cvt_x_kernel<<<(n4x + 255) / 256, 256>>>(x, xf, n4x);
    cvt_w_kernel<<<dim3((n4w + 255) / 256, 4), 256>>>(
        Ws[0], Ws[1], Ws[2], Ws[3], wf);

    const size_t WSZ = (size_t)Dm * Dm;

    // Fused Q/K/V projections (single-pass fp16); Q carries 0.125*log2e.
    const float QSCALE = 0.125f * 1.4426950408889634f;
    const dim3 gqkv(Dm / 128, Mtot / 128, 3);
    hmma_gemm_kernel<true><<<gqkv, 256, GEMM_SMEM>>>(
        xf,
        wf + 0 * WSZ, wf + 1 * WSZ, wf + 2 * WSZ,
        bs[0], bs[1], bs[2],
        nullptr,
        qf, kf, vf,
        QSCALE);

    // Attention (unrolled-x2 single-barrier pipeline, tree reductions)
    const dim3 ga(Sq / 64, Hh, Bc);
    fa_hmma_kernel<<<ga, 128, FA_SMEM>>>(qf, kf, vf, am, cf);

    // Output projection (single-pass fp16)
    const dim3 gg(Dm / 128, Mtot / 128, 1);
    hmma_gemm_kernel<false><<<gg, 256, GEMM_SMEM>>>(
        cf,
        wf + 3 * WSZ, wf + 3 * WSZ, wf + 3 * WSZ,
        bs[3], bs[3], bs[3],
        (float*)d_out,
        nullptr, nullptr, nullptr,
        1.0f);
}